// round 15
// baseline (speedup 1.0000x reference)
#include <cuda_runtime.h>
#include <cuda_fp16.h>
#include <cstdint>

// ============================ problem constants ============================
#define NROWS 16384
#define MCOLS 4096
#define DDIM  128
#define BI    128            // rows per CTA
#define KT    32             // j per pipeline stage
#define NKT   (MCOLS / KT)   // 128 stages
#define THREADS 512          // 8 consumer + 8 producer warps
#define NA   3               // A ring depth
#define NB   7               // B/RE ring depth
#define NMK  6               // mask ring depth
#define LA   6               // unified fetch distance (stages)

// A/B pitch: 32 fp16 (64B) + 16B pad = 80 bytes -> conflict-free ldmatrix
#define PITCH 80
// mask pitch: 32 ints (128B) + 16B pad
#define PITCHM 144

// smem layout (bytes, from 16B-aligned base)
#define A_RING  0            // 3 x 10240 = 30720
#define A_SLOT  10240
#define B_RING  30720        // 7 x 10240 = 71680
#define B_SLOT  10240
#define RE_RING 102400       // 7 x 2048 = 14336
#define RE_SLOT 2048
#define MK_RING 116736       // 6 x 18432 = 110592
#define MK_SLOT 18432
#define ZS_OFF  227328       // 128 floats
#define SMEM_BYTES 227840

// named barriers: FULL_A(s)=1+s (1-3), FREE_A(s)=4+s (4-6),
//                 FREE_B(s)=7+s (7-13), Z-ready=14
#define BAR_SYNC(id)   asm volatile("bar.sync %0, %1;"   :: "r"(id), "r"(THREADS) : "memory")
#define BAR_ARRIVE(id) asm volatile("bar.arrive %0, %1;" :: "r"(id), "r"(THREADS) : "memory")

// ============================ device scratch ===============================
__device__ float g_c[NROWS];    // exp(s_i)
__device__ float g_dd[NROWS];   // exp(0.2 s_i)
__device__ float g_r[MCOLS];    // exp(-0.8 t_j)
__device__ float g_et[MCOLS];   // exp(t_j)
__device__ __half g_UTh[(size_t)DDIM * MCOLS]; // U^T[d][j] = fp16(exp(t_j)*V[j][d])

// ============================ asm helpers ==================================
__device__ __forceinline__ uint32_t smem_to_u32(const void* p) {
    uint32_t a;
    asm("{ .reg .u64 t; cvta.to.shared.u64 t, %1; cvt.u32.u64 %0, t; }"
        : "=r"(a) : "l"(p));
    return a;
}

#define LDM4(r0, r1, r2, r3, addr) \
    asm volatile("ldmatrix.sync.aligned.m8n8.x4.shared.b16 {%0,%1,%2,%3}, [%4];" \
        : "=r"(r0), "=r"(r1), "=r"(r2), "=r"(r3) : "r"(addr))

#define MMA_F16(d, a, b) \
    asm volatile("mma.sync.aligned.m16n8k16.row.col.f32.f16.f16.f32 " \
        "{%0,%1,%2,%3}, {%4,%5,%6,%7}, {%8,%9}, {%0,%1,%2,%3};" \
        : "+f"((d)[0]), "+f"((d)[1]), "+f"((d)[2]), "+f"((d)[3]) \
        : "r"((a)[0]), "r"((a)[1]), "r"((a)[2]), "r"((a)[3]), \
          "r"((b)[0]), "r"((b)[1]))

#define CP_ASYNC16(dst, src) \
    asm volatile("cp.async.cg.shared.global [%0], [%1], 16;" :: "r"(dst), "l"(src))
#define CP_COMMIT()  asm volatile("cp.async.commit_group;" ::: "memory")
#define CP_WAIT5()   asm volatile("cp.async.wait_group 5;" ::: "memory")

// ============================ prep kernels =================================
// fused: rows [0,NROWS) -> self scalars, rows [NROWS,NROWS+MCOLS) -> neigh
__global__ void prep_scalars(const float* __restrict__ sf,
                             const float* __restrict__ fn,
                             const float* __restrict__ a) {
    int row = blockIdx.x * 8 + (threadIdx.x >> 5);
    int lane = threadIdx.x & 31;
    const bool is_self = row < NROWS;
    const float* src = is_self ? &sf[(size_t)row * DDIM]
                               : &fn[(size_t)(row - NROWS) * DDIM];
    const float* w   = is_self ? a : a + DDIM;
    float4 f = *(const float4*)&src[lane * 4];
    float4 ww = *(const float4*)&w[lane * 4];
    float v = f.x * ww.x + f.y * ww.y + f.z * ww.z + f.w * ww.w;
    #pragma unroll
    for (int o = 16; o > 0; o >>= 1) v += __shfl_xor_sync(0xffffffffu, v, o);
    if (lane == 0) {
        if (is_self) {
            g_c[row]  = expf(v);
            g_dd[row] = expf(0.2f * v);
        } else {
            int j = row - NROWS;
            g_r[j]  = expf(-0.8f * v);
            g_et[j] = expf(v);
        }
    }
}

__global__ void prep_ut(const float* __restrict__ fn) {
    int j = blockIdx.x * 256 + threadIdx.x;
    int d = blockIdx.y;
    float v = g_et[j] * fn[(size_t)j * DDIM + d];
    g_UTh[(size_t)d * MCOLS + j] = __float2half_rn(v);
}

// ============================ main kernel ==================================
// A = mask ? max(c_i, dd_i * r_j) : 0   (leaky branch: s+t>0 <=> c > dd*r).
// Stored fp16 RN; Z accumulated in f32 (RN rounding is unbiased -> consistent).
__device__ __forceinline__ float aval(int m, float rr, float cc, float dd) {
    float v = fmaxf(cc, dd * rr);
    return m ? v : 0.0f;
}

// mask fetch for this thread's OWN build rows r0,r0+1 / j-chunk jc, stage kt
// into mask-ring slot m. Same thread consumes -> no barrier needed.
__device__ __forceinline__ void fetch_mask(uint32_t smb,
                                           const char* mrow0, const char* mrow1,
                                           int kt, int m, int r0, int jc) {
    uint32_t mdst = smb + MK_RING + (uint32_t)m * MK_SLOT + r0 * PITCHM + jc * 32u;
    const char* ms0 = mrow0 + (size_t)kt * 128 + jc * 32;
    const char* ms1 = mrow1 + (size_t)kt * 128 + jc * 32;
    CP_ASYNC16(mdst,               ms0);
    CP_ASYNC16(mdst + 16,          ms0 + 16);
    CP_ASYNC16(mdst + PITCHM,      ms1);
    CP_ASYNC16(mdst + PITCHM + 16, ms1 + 16);
}

// B tile + per-warp r/e consts for stage kt into B/RE ring slot b
__device__ __forceinline__ void fetch_BRE(uint32_t smb, const __half* brow,
                                          int kt, int b, int frow, int fh,
                                          int pw, int lane) {
    uint32_t bdst = smb + B_RING + (uint32_t)b * B_SLOT + frow * PITCH + fh * 32u;
    const __half* bsrc = brow + kt * KT;   // brow already offset by fh*16
    CP_ASYNC16(bdst,      bsrc);
    CP_ASYNC16(bdst + 16, bsrc + 8);
    if (lane < 16) {
        const float* cbase = (lane < 8) ? g_r : g_et;
        const int q = lane & 7;
        CP_ASYNC16(smb + RE_RING + (uint32_t)b * RE_SLOT + pw * 256u
                       + (lane < 8 ? 0u : 128u) + q * 16u,
                   cbase + kt * KT + q * 4);
    }
}

__global__ void __launch_bounds__(THREADS, 1)
attn_main(const int* __restrict__ nm, float* __restrict__ out) {
    extern __shared__ char sm[];
    const uint32_t smb = smem_to_u32(sm);
    const int tid = threadIdx.x, lane = tid & 31, wid = tid >> 5;
    const int blockRow = blockIdx.x * BI;
    float* zsm = (float*)(sm + ZS_OFF);

    if (wid >= 8) {
        // ========================= PRODUCER (warps 8-15) =========================
        const int tp = tid - 256;
        const int pw = tp >> 5;                    // producer warp 0-7
        const int frow = tp >> 1, fh = tp & 1;     // B fetch: d-row, 16-j half
        const int r0 = (tp >> 2) * 2, jc = tp & 3; // rows r0,r0+1; j-chunk jc (8 j)
        const float cc0 = g_c[blockRow + r0],  cc1 = g_c[blockRow + r0 + 1];
        const float dd0 = g_dd[blockRow + r0], dd1 = g_dd[blockRow + r0 + 1];
        float z0 = 0.0f, z1 = 0.0f;

        const char* mrow0 = (const char*)(nm + (size_t)(blockRow + r0) * MCOLS);
        const char* mrow1 = (const char*)(nm + (size_t)(blockRow + r0 + 1) * MCOLS);
        const __half* brow = g_UTh + (size_t)frow * MCOLS + fh * 16;

        // prologue: group g carries ALL stage-g fetches (mask + B + RE)
        #pragma unroll
        for (int g = 0; g < LA; g++) {
            fetch_mask(smb, mrow0, mrow1, g, g, r0, jc);
            fetch_BRE(smb, brow, g, g, frow, fh, pw, lane);
            CP_COMMIT();
        }

        int sa = 0, sb = 0, smk = 0;   // ring cursors: kt%3, kt%7, kt%6
        for (int kt = 0; kt < NKT; kt++) {
            // group g completes stage-g fetches; committed = kt+6 groups.
            // wait_group 5 -> complete through group kt -> stage kt ready.
            CP_WAIT5();
            __syncwarp();   // publish this warp's RE copy across its lanes

            if (kt >= NA) BAR_SYNC(4 + sa);          // consumers freed A slot

            // ---- build A(kt) into A slot sa from mask slot smk, RE slot sb ----
            {
                const float4* re = (const float4*)(sm + RE_RING + sb * RE_SLOT + pw * 256);
                const float4 ra = re[jc * 2],     rb = re[jc * 2 + 1];
                const float4 ea = re[8 + jc * 2], eb = re[8 + jc * 2 + 1];
                const char* mks = sm + MK_RING + smk * MK_SLOT + r0 * PITCHM + jc * 32;
                char* dst = sm + A_RING + sa * A_SLOT + r0 * PITCH + jc * 16;
                #pragma unroll
                for (int i = 0; i < 2; i++) {
                    const int4 ma = *(const int4*)(mks + i * PITCHM);
                    const int4 mb = *(const int4*)(mks + i * PITCHM + 16);
                    const float cc = i ? cc1 : cc0, dd = i ? dd1 : dd0;
                    float a0 = aval(ma.x, ra.x, cc, dd);
                    float a1 = aval(ma.y, ra.y, cc, dd);
                    float a2 = aval(ma.z, ra.z, cc, dd);
                    float a3 = aval(ma.w, ra.w, cc, dd);
                    float a4 = aval(mb.x, rb.x, cc, dd);
                    float a5 = aval(mb.y, rb.y, cc, dd);
                    float a6 = aval(mb.z, rb.z, cc, dd);
                    float a7 = aval(mb.w, rb.w, cc, dd);
                    float z = a0 * ea.x + a1 * ea.y + a2 * ea.z + a3 * ea.w
                            + a4 * eb.x + a5 * eb.y + a6 * eb.z + a7 * eb.w;
                    if (i) z1 += z; else z0 += z;
                    __half2 h0 = __floats2half2_rn(a0, a1);
                    __half2 h1 = __floats2half2_rn(a2, a3);
                    __half2 h2 = __floats2half2_rn(a4, a5);
                    __half2 h3 = __floats2half2_rn(a6, a7);
                    uint4 q;
                    q.x = *(uint32_t*)&h0; q.y = *(uint32_t*)&h1;
                    q.z = *(uint32_t*)&h2; q.w = *(uint32_t*)&h3;
                    *(uint4*)(dst + i * PITCH) = q;
                }
            }
            BAR_ARRIVE(1 + sa);                      // FULL_A(sa)

            const int kf = kt + LA;
            if (kf < NKT) {
                int bs = sb + LA; if (bs >= NB) bs -= NB;   // slot (kt+6)%7
                if (kf >= NB) BAR_SYNC(7 + bs);      // consumers freed B slot
                fetch_mask(smb, mrow0, mrow1, kf, smk, r0, jc);
                fetch_BRE(smb, brow, kf, bs, frow, fh, pw, lane);
            }
            CP_COMMIT();                             // one group per stage, always
            sa  = (sa  + 1 == NA)  ? 0 : sa  + 1;
            sb  = (sb  + 1 == NB)  ? 0 : sb  + 1;
            smk = (smk + 1 == NMK) ? 0 : smk + 1;
        }

        // ---- Z: reduce over 4 j-chunk lanes, publish ----
        z0 += __shfl_xor_sync(0xffffffffu, z0, 1);
        z0 += __shfl_xor_sync(0xffffffffu, z0, 2);
        z1 += __shfl_xor_sync(0xffffffffu, z1, 1);
        z1 += __shfl_xor_sync(0xffffffffu, z1, 2);
        if ((lane & 3) == 0) { zsm[r0] = z0; zsm[r0 + 1] = z1; }
        BAR_ARRIVE(14);                              // Z ready
    } else {
        // ========================= CONSUMER (warps 0-7) =========================
        const int mi = wid & 1, ni = wid >> 1;       // 64m x 32n warp tile, K unsplit
        float acc[4][4][4];
        #pragma unroll
        for (int f = 0; f < 4; f++)
            #pragma unroll
            for (int n8 = 0; n8 < 4; n8++)
                #pragma unroll
                for (int q = 0; q < 4; q++) acc[f][n8][q] = 0.0f;

        uint32_t aoff[4], boff[2];
        #pragma unroll
        for (int f = 0; f < 4; f++)
            aoff[f] = (uint32_t)((mi * 64 + f * 16 + (lane & 15)) * PITCH + (lane >> 4) * 16);
        #pragma unroll
        for (int p = 0; p < 2; p++)
            boff[p] = (uint32_t)((ni * 32 + p * 16 + (lane & 7) + ((lane >> 4) << 3)) * PITCH
                                 + ((lane >> 3) & 1) * 16);

        int sa = 0, sb = 0;
        for (int kt = 0; kt < NKT; kt++) {
            BAR_SYNC(1 + sa);                         // wait FULL_A(sa)
            const uint32_t Ab = smb + A_RING + sa * A_SLOT;
            const uint32_t Bb = smb + B_RING + sb * B_SLOT;
            #pragma unroll
            for (int kk = 0; kk < 2; kk++) {          // two k16 steps cover KT=32
                const uint32_t koff = kk * 32;        // 16 fp16 = 32 bytes
                uint32_t af[4][4], bf[4][2];
                #pragma unroll
                for (int f = 0; f < 4; f++)
                    LDM4(af[f][0], af[f][1], af[f][2], af[f][3], Ab + aoff[f] + koff);
                #pragma unroll
                for (int p = 0; p < 2; p++)
                    LDM4(bf[2 * p][0], bf[2 * p][1], bf[2 * p + 1][0], bf[2 * p + 1][1],
                         Bb + boff[p] + koff);
                #pragma unroll
                for (int f = 0; f < 4; f++)
                    #pragma unroll
                    for (int n8 = 0; n8 < 4; n8++)
                        MMA_F16(acc[f][n8], af[f], bf[n8]);
            }
            BAR_ARRIVE(4 + sa);                       // FREE_A(sa)
            BAR_ARRIVE(7 + sb);                       // FREE_B(sb)
            sa = (sa + 1 == NA) ? 0 : sa + 1;
            sb = (sb + 1 == NB) ? 0 : sb + 1;
        }

        BAR_SYNC(14);                                 // Z ready (drains zsm STS)

        // ---- epilogue: scale by 1/Z, store ----
        #pragma unroll
        for (int f = 0; f < 4; f++) {
            const int row0 = mi * 64 + f * 16 + (lane >> 2);
            const float zz0 = zsm[row0], zz1 = zsm[row0 + 8];
            const float i0 = (zz0 > 0.0f) ? 1.0f / zz0 : 0.0f;
            const float i1 = (zz1 > 0.0f) ? 1.0f / zz1 : 0.0f;
            const size_t go0 = (size_t)(blockRow + row0) * DDIM;
            const size_t go1 = go0 + (size_t)8 * DDIM;
            #pragma unroll
            for (int n8 = 0; n8 < 4; n8++) {
                const int col = ni * 32 + n8 * 8 + (lane & 3) * 2;
                *(float2*)&out[go0 + col] =
                    make_float2(acc[f][n8][0] * i0, acc[f][n8][1] * i0);
                *(float2*)&out[go1 + col] =
                    make_float2(acc[f][n8][2] * i1, acc[f][n8][3] * i1);
            }
        }
    }
}

// ============================ launch =======================================
extern "C" void kernel_launch(void* const* d_in, const int* in_sizes, int n_in,
                              void* d_out, int out_size) {
    const float* sf = (const float*)d_in[0];   // self_feats      [16384,128] f32
    const float* fn = (const float*)d_in[1];   // features_neighs [4096,128]  f32
    const int*   nm = (const int*)d_in[2];     // neigh_matrix    [16384,4096] i32
    const float* a  = (const float*)d_in[3];   // a [256] f32
    float* out = (float*)d_out;

    prep_scalars<<<(NROWS + MCOLS) / 8, 256>>>(sf, fn, a);
    prep_ut<<<dim3(MCOLS / 256, DDIM), 256>>>(fn);

    cudaFuncSetAttribute(attn_main, cudaFuncAttributeMaxDynamicSharedMemorySize, SMEM_BYTES);
    attn_main<<<NROWS / BI, THREADS, SMEM_BYTES>>>(nm, out);
}

// round 16
// speedup vs baseline: 1.1328x; 1.1328x over previous
#include <cuda_runtime.h>
#include <cuda_fp16.h>
#include <cstdint>

// ============================ problem constants ============================
#define NROWS 16384
#define MCOLS 4096
#define DDIM  128
#define BI    128            // rows per CTA
#define KT    32             // j per pipeline stage
#define NKT   (MCOLS / KT)   // 128 stages
#define THREADS 512          // 8 consumer + 8 producer warps
#define NSTG 5               // A/B ring depth
#define LA_B 4               // B fetch distance (stages)
#define NMK  6               // mask ring depth (= mask fetch distance)

// A/B pitch: 32 fp16 (64B) + 16B pad = 80 bytes -> conflict-free ldmatrix
#define PITCH 80
// mask pitch: 32 ints (128B) + 16B pad
#define PITCHM 144

// smem layout (bytes, from 16B-aligned base)
#define A_OFF  0             // 128 x 80 = 10240
#define B_OFF  10240         // 128 x 80 = 10240
#define RE_OFF 20480         // 8 producer-warp copies x 256B = 2048
#define STG    22528         // A/B stage stride; ring = 5 x 22528 = 112640
#define MK_RING 112640       // mask ring: 6 slots x (128 x 144 = 18432) = 110592
#define MK_SLOT 18432
#define ZS_OFF  223232       // 128 floats
#define SMEM_BYTES 223744

// named barriers: FULL(s)=1+s (1-5), FREE(s)=6+s (6-10), Z-ready=11
#define BAR_SYNC(id)   asm volatile("bar.sync %0, %1;"   :: "r"(id), "r"(THREADS) : "memory")
#define BAR_ARRIVE(id) asm volatile("bar.arrive %0, %1;" :: "r"(id), "r"(THREADS) : "memory")

// ============================ device scratch ===============================
__device__ float g_c[NROWS];    // exp(s_i)
__device__ float g_dd[NROWS];   // exp(0.2 s_i)
__device__ float g_r[MCOLS];    // exp(-0.8 t_j)
__device__ float g_et[MCOLS];   // exp(t_j)
__device__ __half g_UTh[(size_t)DDIM * MCOLS]; // U^T[d][j] = fp16(exp(t_j)*V[j][d])

// ============================ asm helpers ==================================
__device__ __forceinline__ uint32_t smem_to_u32(const void* p) {
    uint32_t a;
    asm("{ .reg .u64 t; cvta.to.shared.u64 t, %1; cvt.u32.u64 %0, t; }"
        : "=r"(a) : "l"(p));
    return a;
}

#define LDM4(r0, r1, r2, r3, addr) \
    asm volatile("ldmatrix.sync.aligned.m8n8.x4.shared.b16 {%0,%1,%2,%3}, [%4];" \
        : "=r"(r0), "=r"(r1), "=r"(r2), "=r"(r3) : "r"(addr))

#define MMA_F16(d, a, b) \
    asm volatile("mma.sync.aligned.m16n8k16.row.col.f32.f16.f16.f32 " \
        "{%0,%1,%2,%3}, {%4,%5,%6,%7}, {%8,%9}, {%0,%1,%2,%3};" \
        : "+f"((d)[0]), "+f"((d)[1]), "+f"((d)[2]), "+f"((d)[3]) \
        : "r"((a)[0]), "r"((a)[1]), "r"((a)[2]), "r"((a)[3]), \
          "r"((b)[0]), "r"((b)[1]))

#define CP_ASYNC16(dst, src) \
    asm volatile("cp.async.cg.shared.global [%0], [%1], 16;" :: "r"(dst), "l"(src))
#define CP_COMMIT()  asm volatile("cp.async.commit_group;" ::: "memory")
#define CP_WAIT3()   asm volatile("cp.async.wait_group 3;" ::: "memory")

// ============================ prep kernels =================================
// self scalars: each warp handles 2 rows with both loads in flight (MLP=2)
__global__ void prep_self(const float* __restrict__ sf, const float* __restrict__ a) {
    const int wg = blockIdx.x * 8 + (threadIdx.x >> 5);
    const int lane = threadIdx.x & 31;
    const int row0 = wg * 2;
    float4 f0 = *(const float4*)&sf[(size_t)row0 * DDIM + lane * 4];
    float4 f1 = *(const float4*)&sf[(size_t)(row0 + 1) * DDIM + lane * 4];
    float4 w  = *(const float4*)&a[lane * 4];
    float v0 = f0.x * w.x + f0.y * w.y + f0.z * w.z + f0.w * w.w;
    float v1 = f1.x * w.x + f1.y * w.y + f1.z * w.z + f1.w * w.w;
    #pragma unroll
    for (int o = 16; o > 0; o >>= 1) {
        v0 += __shfl_xor_sync(0xffffffffu, v0, o);
        v1 += __shfl_xor_sync(0xffffffffu, v1, o);
    }
    if (lane == 0) {
        g_c[row0]      = expf(v0);
        g_dd[row0]     = expf(0.2f * v0);
        g_c[row0 + 1]  = expf(v1);
        g_dd[row0 + 1] = expf(0.2f * v1);
    }
}

// fused neigh pass: coalesced fn tile load -> t_j/r/et -> transposed fp16 U^T
#define UTB 32   // j rows per block
__global__ void prep_ut_fused(const float* __restrict__ fn,
                              const float* __restrict__ a) {
    __shared__ float tile[UTB][132];   // 132-float pitch (16B-aligned rows)
    __shared__ float ets[UTB];
    const int tid = threadIdx.x;
    const int jb = blockIdx.x * UTB;

    // phase 1: coalesced row loads (32 rows x 128 floats = 1024 float4)
    #pragma unroll
    for (int it = 0; it < 4; it++) {
        const int idx = it * 256 + tid;          // 0..1023
        const int row = idx >> 5, c4 = (idx & 31) * 4;
        *(float4*)&tile[row][c4] = *(const float4*)&fn[(size_t)(jb + row) * DDIM + c4];
    }
    __syncthreads();

    // phase 2: t_j = fn[j] . a_neigh  (8 threads per row, 16 elems each)
    {
        const int row = tid >> 3, q = tid & 7;
        float s = 0.0f;
        #pragma unroll
        for (int k = 0; k < 4; k++) {
            float4 f = *(const float4*)&tile[row][q * 16 + k * 4];
            float4 w = *(const float4*)&a[DDIM + q * 16 + k * 4];
            s += f.x * w.x + f.y * w.y + f.z * w.z + f.w * w.w;
        }
        s += __shfl_xor_sync(0xffffffffu, s, 1);
        s += __shfl_xor_sync(0xffffffffu, s, 2);
        s += __shfl_xor_sync(0xffffffffu, s, 4);
        if (q == 0) {
            const float et = expf(s);
            g_r[jb + row]  = expf(-0.8f * s);
            g_et[jb + row] = et;
            ets[row] = et;
        }
    }
    __syncthreads();

    // phase 3: write U^T[d][jb..jb+31] as fp16, 16B stores (8 j per uint4)
    #pragma unroll
    for (int it = 0; it < 2; it++) {
        const int u = it * 256 + tid;            // 0..511
        const int d = u >> 2, j0 = (u & 3) * 8;
        uint4 q;
        __half2 h;
        h = __floats2half2_rn(ets[j0    ] * tile[j0    ][d],
                              ets[j0 + 1] * tile[j0 + 1][d]); q.x = *(uint32_t*)&h;
        h = __floats2half2_rn(ets[j0 + 2] * tile[j0 + 2][d],
                              ets[j0 + 3] * tile[j0 + 3][d]); q.y = *(uint32_t*)&h;
        h = __floats2half2_rn(ets[j0 + 4] * tile[j0 + 4][d],
                              ets[j0 + 5] * tile[j0 + 5][d]); q.z = *(uint32_t*)&h;
        h = __floats2half2_rn(ets[j0 + 6] * tile[j0 + 6][d],
                              ets[j0 + 7] * tile[j0 + 7][d]); q.w = *(uint32_t*)&h;
        *(uint4*)&g_UTh[(size_t)d * MCOLS + jb + j0] = q;
    }
}

// ============================ main kernel ==================================
// A = mask ? max(c_i, dd_i * r_j) : 0   (leaky branch: s+t>0 <=> c > dd*r).
// Stored fp16 RN; Z accumulated in f32 (RN rounding is unbiased -> consistent).
__device__ __forceinline__ float aval(int m, float rr, float cc, float dd) {
    float v = fmaxf(cc, dd * rr);
    return m ? v : 0.0f;
}

// mask fetch for this thread's OWN build rows r0,r0+1 / j-chunk jc, stage kt
// into mask-ring slot m. Same thread consumes -> no barrier needed.
__device__ __forceinline__ void fetch_mask(uint32_t smb,
                                           const char* mrow0, const char* mrow1,
                                           int kt, int m, int r0, int jc) {
    uint32_t mdst = smb + MK_RING + (uint32_t)m * MK_SLOT + r0 * PITCHM + jc * 32u;
    const char* ms0 = mrow0 + (size_t)kt * 128 + jc * 32;
    const char* ms1 = mrow1 + (size_t)kt * 128 + jc * 32;
    CP_ASYNC16(mdst,               ms0);
    CP_ASYNC16(mdst + 16,          ms0 + 16);
    CP_ASYNC16(mdst + PITCHM,      ms1);
    CP_ASYNC16(mdst + PITCHM + 16, ms1 + 16);
}

// B tile + per-warp r/e consts for stage kt into A/B ring slot s
__device__ __forceinline__ void fetch_BRE(uint32_t smb, const __half* brow,
                                          int kt, int s, int frow, int fh,
                                          int pw, int lane) {
    const uint32_t base = smb + s * STG;
    uint32_t bdst = base + B_OFF + frow * PITCH + fh * 32u;
    const __half* bsrc = brow + kt * KT;   // brow already offset by fh*16
    CP_ASYNC16(bdst,      bsrc);
    CP_ASYNC16(bdst + 16, bsrc + 8);
    if (lane < 16) {
        const float* cbase = (lane < 8) ? g_r : g_et;
        const int q = lane & 7;
        CP_ASYNC16(base + RE_OFF + pw * 256u + (lane < 8 ? 0u : 128u) + q * 16u,
                   cbase + kt * KT + q * 4);
    }
}

__global__ void __launch_bounds__(THREADS, 1)
attn_main(const int* __restrict__ nm, float* __restrict__ out) {
    extern __shared__ char sm[];
    const uint32_t smb = smem_to_u32(sm);
    const int tid = threadIdx.x, lane = tid & 31, wid = tid >> 5;
    const int blockRow = blockIdx.x * BI;
    float* zsm = (float*)(sm + ZS_OFF);

    if (wid >= 8) {
        // ========================= PRODUCER (warps 8-15) =========================
        const int tp = tid - 256;
        const int pw = tp >> 5;                    // producer warp 0-7
        const int frow = tp >> 1, fh = tp & 1;     // B fetch: d-row, 16-j half
        const int r0 = (tp >> 2) * 2, jc = tp & 3; // rows r0,r0+1; j-chunk jc (8 j)
        const float cc0 = g_c[blockRow + r0],  cc1 = g_c[blockRow + r0 + 1];
        const float dd0 = g_dd[blockRow + r0], dd1 = g_dd[blockRow + r0 + 1];
        float z0 = 0.0f, z1 = 0.0f;

        const char* mrow0 = (const char*)(nm + (size_t)(blockRow + r0) * MCOLS);
        const char* mrow1 = (const char*)(nm + (size_t)(blockRow + r0 + 1) * MCOLS);
        const __half* brow = g_UTh + (size_t)frow * MCOLS + fh * 16;

        // prologue: 6 commit groups; group g carries mask(g) (+ B(g) for g<4)
        #pragma unroll
        for (int g = 0; g < NMK; g++) {
            fetch_mask(smb, mrow0, mrow1, g, g, r0, jc);
            if (g < LA_B) fetch_BRE(smb, brow, g, g, frow, fh, pw, lane);
            CP_COMMIT();
        }

        int s = 0;          // A/B ring slot (kt % 5)
        int mslot = 0;      // mask ring slot (kt % 6)
        for (int kt = 0; kt < NKT; kt++) {
            // groups: mask(kt) in group kt, B(kt) in group <= kt+2; committed = 6+kt
            // wait_group 3 completes through group kt+2 -> both ready.
            CP_WAIT3();
            __syncwarp();   // publish this warp's RE copy across its lanes

            // ---- build A(kt) into A/B slot s from mask slot mslot ----
            {
                const float4* re = (const float4*)(sm + s * STG + RE_OFF + pw * 256);
                const float4 ra = re[jc * 2],     rb = re[jc * 2 + 1];
                const float4 ea = re[8 + jc * 2], eb = re[8 + jc * 2 + 1];
                const char* mks = sm + MK_RING + mslot * MK_SLOT + r0 * PITCHM + jc * 32;
                char* dst = sm + s * STG + A_OFF + r0 * PITCH + jc * 16;
                #pragma unroll
                for (int i = 0; i < 2; i++) {
                    const int4 ma = *(const int4*)(mks + i * PITCHM);
                    const int4 mb = *(const int4*)(mks + i * PITCHM + 16);
                    const float cc = i ? cc1 : cc0, dd = i ? dd1 : dd0;
                    float a0 = aval(ma.x, ra.x, cc, dd);
                    float a1 = aval(ma.y, ra.y, cc, dd);
                    float a2 = aval(ma.z, ra.z, cc, dd);
                    float a3 = aval(ma.w, ra.w, cc, dd);
                    float a4 = aval(mb.x, rb.x, cc, dd);
                    float a5 = aval(mb.y, rb.y, cc, dd);
                    float a6 = aval(mb.z, rb.z, cc, dd);
                    float a7 = aval(mb.w, rb.w, cc, dd);
                    float z = a0 * ea.x + a1 * ea.y + a2 * ea.z + a3 * ea.w
                            + a4 * eb.x + a5 * eb.y + a6 * eb.z + a7 * eb.w;
                    if (i) z1 += z; else z0 += z;
                    __half2 h0 = __floats2half2_rn(a0, a1);
                    __half2 h1 = __floats2half2_rn(a2, a3);
                    __half2 h2 = __floats2half2_rn(a4, a5);
                    __half2 h3 = __floats2half2_rn(a6, a7);
                    uint4 q;
                    q.x = *(uint32_t*)&h0; q.y = *(uint32_t*)&h1;
                    q.z = *(uint32_t*)&h2; q.w = *(uint32_t*)&h3;
                    *(uint4*)(dst + i * PITCH) = q;
                }
            }
            BAR_ARRIVE(1 + s);                       // FULL(s)

            // mask prefetch: stage kt+6 into the slot just consumed (same thread)
            const int kf6 = kt + NMK;
            if (kf6 < NKT)
                fetch_mask(smb, mrow0, mrow1, kf6, mslot, r0, jc);
            // B prefetch: stage kt+4 into slot (kt+4)%5 after consumers free it
            const int kf4 = kt + LA_B;
            if (kf4 < NKT) {
                int s4 = s + LA_B; if (s4 >= NSTG) s4 -= NSTG;
                if (kf4 >= NSTG) BAR_SYNC(6 + s4);   // consumers freed slot s4
                fetch_BRE(smb, brow, kf4, s4, frow, fh, pw, lane);
            }
            CP_COMMIT();                             // one group per stage, always
            s = (s + 1 == NSTG) ? 0 : s + 1;
            mslot = (mslot + 1 == NMK) ? 0 : mslot + 1;
        }

        // ---- Z: reduce over 4 j-chunk lanes, publish ----
        z0 += __shfl_xor_sync(0xffffffffu, z0, 1);
        z0 += __shfl_xor_sync(0xffffffffu, z0, 2);
        z1 += __shfl_xor_sync(0xffffffffu, z1, 1);
        z1 += __shfl_xor_sync(0xffffffffu, z1, 2);
        if ((lane & 3) == 0) { zsm[r0] = z0; zsm[r0 + 1] = z1; }
        BAR_ARRIVE(11);                              // Z ready
    } else {
        // ========================= CONSUMER (warps 0-7) =========================
        const int mi = wid & 1, ni = wid >> 1;       // 64m x 32n warp tile, K unsplit
        float acc[4][4][4];
        #pragma unroll
        for (int f = 0; f < 4; f++)
            #pragma unroll
            for (int n8 = 0; n8 < 4; n8++)
                #pragma unroll
                for (int q = 0; q < 4; q++) acc[f][n8][q] = 0.0f;

        uint32_t aoff[4], boff[2];
        #pragma unroll
        for (int f = 0; f < 4; f++)
            aoff[f] = (uint32_t)((mi * 64 + f * 16 + (lane & 15)) * PITCH + (lane >> 4) * 16);
        #pragma unroll
        for (int p = 0; p < 2; p++)
            boff[p] = (uint32_t)((ni * 32 + p * 16 + (lane & 7) + ((lane >> 4) << 3)) * PITCH
                                 + ((lane >> 3) & 1) * 16);

        int s = 0;
        for (int kt = 0; kt < NKT; kt++) {
            BAR_SYNC(1 + s);                          // wait FULL(s)
            const uint32_t Ab = smb + s * STG + A_OFF;
            const uint32_t Bb = smb + s * STG + B_OFF;
            #pragma unroll
            for (int kk = 0; kk < 2; kk++) {          // two k16 steps cover KT=32
                const uint32_t koff = kk * 32;        // 16 fp16 = 32 bytes
                uint32_t af[4][4], bf[4][2];
                #pragma unroll
                for (int f = 0; f < 4; f++)
                    LDM4(af[f][0], af[f][1], af[f][2], af[f][3], Ab + aoff[f] + koff);
                #pragma unroll
                for (int p = 0; p < 2; p++)
                    LDM4(bf[2 * p][0], bf[2 * p][1], bf[2 * p + 1][0], bf[2 * p + 1][1],
                         Bb + boff[p] + koff);
                #pragma unroll
                for (int f = 0; f < 4; f++)
                    #pragma unroll
                    for (int n8 = 0; n8 < 4; n8++)
                        MMA_F16(acc[f][n8], af[f], bf[n8]);
            }
            BAR_ARRIVE(6 + s);                        // FREE(s)
            s = (s + 1 == NSTG) ? 0 : s + 1;
        }

        BAR_SYNC(11);                                 // Z ready (drains zsm STS)

        // ---- epilogue: scale by 1/Z, store ----
        #pragma unroll
        for (int f = 0; f < 4; f++) {
            const int row0 = mi * 64 + f * 16 + (lane >> 2);
            const float zz0 = zsm[row0], zz1 = zsm[row0 + 8];
            const float i0 = (zz0 > 0.0f) ? 1.0f / zz0 : 0.0f;
            const float i1 = (zz1 > 0.0f) ? 1.0f / zz1 : 0.0f;
            const size_t go0 = (size_t)(blockRow + row0) * DDIM;
            const size_t go1 = go0 + (size_t)8 * DDIM;
            #pragma unroll
            for (int n8 = 0; n8 < 4; n8++) {
                const int col = ni * 32 + n8 * 8 + (lane & 3) * 2;
                *(float2*)&out[go0 + col] =
                    make_float2(acc[f][n8][0] * i0, acc[f][n8][1] * i0);
                *(float2*)&out[go1 + col] =
                    make_float2(acc[f][n8][2] * i1, acc[f][n8][3] * i1);
            }
        }
    }
}

// ============================ launch =======================================
extern "C" void kernel_launch(void* const* d_in, const int* in_sizes, int n_in,
                              void* d_out, int out_size) {
    const float* sf = (const float*)d_in[0];   // self_feats      [16384,128] f32
    const float* fn = (const float*)d_in[1];   // features_neighs [4096,128]  f32
    const int*   nm = (const int*)d_in[2];     // neigh_matrix    [16384,4096] i32
    const float* a  = (const float*)d_in[3];   // a [256] f32
    float* out = (float*)d_out;

    prep_self<<<NROWS / 16, 256>>>(sf, a);
    prep_ut_fused<<<MCOLS / UTB, 256>>>(fn, a);

    cudaFuncSetAttribute(attn_main, cudaFuncAttributeMaxDynamicSharedMemorySize, SMEM_BYTES);
    attn_main<<<NROWS / BI, THREADS, SMEM_BYTES>>>(nm, out);
}